// round 11
// baseline (speedup 1.0000x reference)
#include <cuda_runtime.h>
#include <cuda_fp16.h>
#include <math.h>
#include <stdint.h>

#define T_SEQ 4096
#define C_DIM 2048
#define KV_DIM 512
#define QKV_N 3072
#define NH 16
#define NKV 4
#define HD 128
#define HALF 64
#define WIN 64
#define KDIM 2048
#define KT2 32                // 2048 / 64

// Scratch (no runtime allocation allowed)
__device__ float  g_Q[T_SEQ * C_DIM];
__device__ float  g_K[T_SEQ * KV_DIM];
__device__ float  g_V[T_SEQ * KV_DIM];
__device__ __half g_AOH[T_SEQ * C_DIM];        // attention output, fp16
__device__ __half g_XH[T_SEQ * C_DIM];         // x, fp16
__device__ __half g_WH[QKV_N * KDIM];          // [wq|wk|wv]^T  [N][K] fp16
__device__ __half g_WOH[C_DIM * KDIM];         // wo^T          [N][K] fp16
__device__ float2 g_RC[T_SEQ * HALF];          // rope (cos,sin) table

// ---------------------------------------------------------------------------
// One-time prep kernels
// ---------------------------------------------------------------------------
__global__ void rc_kernel() {
    int idx = blockIdx.x * blockDim.x + threadIdx.x;
    if (idx >= T_SEQ * HALF) return;
    int t = idx >> 6;
    int j = idx & 63;
    float inv = powf(10000.0f, -(float)j / (float)HALF);
    float s, c;
    sincosf((float)t * inv, &s, &c);
    g_RC[idx] = make_float2(c, s);
}

__global__ void x_to_half(const float4* __restrict__ src, int n4) {
    int i = blockIdx.x * blockDim.x + threadIdx.x;
    if (i >= n4) return;
    float4 v = src[i];
    __half2* dst = (__half2*)(g_XH + (size_t)i * 4);
    dst[0] = __floats2half2_rn(v.x, v.y);
    dst[1] = __floats2half2_rn(v.z, v.w);
}

// Transpose + convert: g_WH[n][k] = half(src[k][n]); src picked per n-region.
__global__ void build_wt(const float* __restrict__ wq, const float* __restrict__ wk,
                         const float* __restrict__ wv) {
    __shared__ float tile[32][33];
    int k0 = blockIdx.x * 32;
    int n0 = blockIdx.y * 32;
    int tx = threadIdx.x, ty = threadIdx.y;
    const float* src;
    int nb, noff;
    if (n0 < C_DIM)               { src = wq; nb = C_DIM;  noff = 0; }
    else if (n0 < C_DIM + KV_DIM) { src = wk; nb = KV_DIM; noff = C_DIM; }
    else                          { src = wv; nb = KV_DIM; noff = C_DIM + KV_DIM; }
#pragma unroll
    for (int j = 0; j < 4; j++)
        tile[ty + j * 8][tx] =
            src[(size_t)(k0 + ty + j * 8) * nb + (n0 - noff + tx)];
    __syncthreads();
#pragma unroll
    for (int j = 0; j < 4; j++)
        g_WH[(size_t)(n0 + ty + j * 8) * KDIM + k0 + tx] =
            __float2half(tile[tx][ty + j * 8]);
}

__global__ void build_wot(const float* __restrict__ wo) {
    __shared__ float tile[32][33];
    int k0 = blockIdx.x * 32;
    int n0 = blockIdx.y * 32;
    int tx = threadIdx.x, ty = threadIdx.y;
#pragma unroll
    for (int j = 0; j < 4; j++)
        tile[ty + j * 8][tx] = wo[(size_t)(k0 + ty + j * 8) * C_DIM + n0 + tx];
    __syncthreads();
#pragma unroll
    for (int j = 0; j < 4; j++)
        g_WOH[(size_t)(n0 + ty + j * 8) * KDIM + k0 + tx] =
            __float2half(tile[tx][ty + j * 8]);
}

// ---------------------------------------------------------------------------
// FP16 mma.sync GEMM with ldmatrix fragment loads, K-chunk 64.
// C[M,N] = A[M,K] @ Bt[N,K]^T, fp32 accumulate.
// CTA tile 128x128x64, 256 threads (8 warps 2x4), warp tile 64x32,
// mma.m16n8k16. Both tiles K-major, 72-half padded rows (36-word stride ->
// conflict-free LDSM). cp.async 3-stage pipeline, 2 CTAs/SM.
// mode 0: plain fp32 store. mode 1: QKV epilogue (rope + route).
// ---------------------------------------------------------------------------
#define STAGES 3
#define SROW 72                               // halves per smem row (64 + 8 pad)
#define TILE_BYTES (128 * SROW * 2)           // 18432
#define STAGE_BYTES (2 * TILE_BYTES)          // 36864
#define SMEM_BYTES (STAGES * STAGE_BYTES)     // 110592

__device__ __forceinline__ void cp16(uint32_t dst, const __half* src) {
    asm volatile("cp.async.cg.shared.global [%0], [%1], 16;\n" :: "r"(dst), "l"(src));
}

#define LDSM4(r0, r1, r2, r3, addr)                                            \
    asm volatile("ldmatrix.sync.aligned.m8n8.x4.shared.b16 {%0,%1,%2,%3}, [%4];" \
                 : "=r"(r0), "=r"(r1), "=r"(r2), "=r"(r3) : "r"(addr))

__device__ __forceinline__ void mma_f16(float c[4], const uint32_t a[4],
                                        const uint32_t b[2]) {
    asm volatile(
        "mma.sync.aligned.m16n8k16.row.col.f32.f16.f16.f32 "
        "{%0,%1,%2,%3}, {%4,%5,%6,%7}, {%8,%9}, {%0,%1,%2,%3};\n"
        : "+f"(c[0]), "+f"(c[1]), "+f"(c[2]), "+f"(c[3])
        : "r"(a[0]), "r"(a[1]), "r"(a[2]), "r"(a[3]), "r"(b[0]), "r"(b[1]));
}

__device__ __forceinline__ void qkv_store(int t, int col, float v0, float v1) {
    if (col < C_DIM) {
        int jj = (col & 127) >> 1;
        float2 cs = g_RC[t * HALF + jj];
        *(float2*)&g_Q[(size_t)t * C_DIM + col] =
            make_float2(v0 * cs.x - v1 * cs.y, v0 * cs.y + v1 * cs.x);
    } else if (col < C_DIM + KV_DIM) {
        int kc = col - C_DIM;
        int jj = (kc & 127) >> 1;
        float2 cs = g_RC[t * HALF + jj];
        *(float2*)&g_K[(size_t)t * KV_DIM + kc] =
            make_float2(v0 * cs.x - v1 * cs.y, v0 * cs.y + v1 * cs.x);
    } else {
        int vc = col - C_DIM - KV_DIM;
        *(float2*)&g_V[(size_t)t * KV_DIM + vc] = make_float2(v0, v1);
    }
}

__global__ void __launch_bounds__(256, 2) gemm_f16(const __half* __restrict__ A,
                                                   const __half* __restrict__ Bt,
                                                   float* __restrict__ C,
                                                   int N, int mode) {
    extern __shared__ char smem[];
    uint32_t smem_u;
    asm("{.reg .u64 t; cvta.to.shared.u64 t, %1; cvt.u32.u64 %0, t;}"
        : "=r"(smem_u) : "l"(smem));

    const int tid = threadIdx.x;
    const int bm = blockIdx.y * 128;
    const int bn = blockIdx.x * 128;
    const int warp = tid >> 5;
    const int lane = tid & 31;
    const int wm = warp >> 2;     // 0..1
    const int wn = warp & 3;      // 0..3
    const int g  = lane >> 2;     // 0..7
    const int tg = lane & 3;      // 0..3

    // ldmatrix per-lane address constants (byte offsets within stage)
    const int mi = lane >> 3;     // matrix index 0..3
    const int rw = lane & 7;      // row within matrix
    // A: m0=rows0-7/k0-7, m1=rows8-15/k0-7, m2=rows0-7/k8-15, m3=rows8-15/k8-15
    const uint32_t aoff0 =
        (uint32_t)(((wm * 64 + ((mi & 1) << 3) + rw) * SROW + ((mi >> 1) << 3)) * 2);
    // B: m0=(j,k0-7), m1=(j,k8-15), m2=(j+1,k0-7), m3=(j+1,k8-15)
    const uint32_t boff0 =
        (uint32_t)(((wn * 32 + ((mi >> 1) << 3) + rw) * SROW + ((mi & 1) << 3)) * 2) +
        TILE_BYTES;

    // loader mapping: 128 rows x 8 chunks(16B) per tile; each thread does
    // 4 contiguous chunks of A and 4 of B.
    const int lrow = tid >> 1;          // 0..127
    const int lhalfk = (tid & 1) * 32;  // halves offset within row: 0 or 32
    const __half* ap = A + (size_t)(bm + lrow) * KDIM + lhalfk;
    const __half* bp = Bt + (size_t)(bn + lrow) * KDIM + lhalfk;
    const uint32_t soff = (uint32_t)((lrow * SROW + lhalfk) * 2);

    float acc[4][4][4];
#pragma unroll
    for (int i = 0; i < 4; i++)
#pragma unroll
        for (int j = 0; j < 4; j++)
#pragma unroll
            for (int r = 0; r < 4; r++) acc[i][j][r] = 0.f;

    // prologue: stages 0,1
#pragma unroll
    for (int s = 0; s < STAGES - 1; s++) {
        uint32_t base = smem_u + (uint32_t)s * STAGE_BYTES;
#pragma unroll
        for (int v = 0; v < 4; v++) {
            cp16(base + soff + v * 16, ap + v * 8);
            cp16(base + TILE_BYTES + soff + v * 16, bp + v * 8);
        }
        asm volatile("cp.async.commit_group;\n" ::);
        ap += 64;
        bp += 64;
    }

    int st = 0;
    int wst = STAGES - 1;
    for (int kt = 0; kt < KT2; kt++) {
        if (kt < KT2 - 1)
            asm volatile("cp.async.wait_group 1;\n" ::);
        else
            asm volatile("cp.async.wait_group 0;\n" ::);
        __syncthreads();

        if (kt + STAGES - 1 < KT2) {
            uint32_t base = smem_u + (uint32_t)wst * STAGE_BYTES;
#pragma unroll
            for (int v = 0; v < 4; v++) {
                cp16(base + soff + v * 16, ap + v * 8);
                cp16(base + TILE_BYTES + soff + v * 16, bp + v * 8);
            }
            asm volatile("cp.async.commit_group;\n" ::);
            ap += 64;
            bp += 64;
            wst = (wst == STAGES - 1) ? 0 : wst + 1;
        }

        const uint32_t sbase = smem_u + (uint32_t)st * STAGE_BYTES;
        st = (st == STAGES - 1) ? 0 : st + 1;

#pragma unroll
        for (int s = 0; s < 4; s++) {       // four k16 steps per k-chunk
            uint32_t af[4][4], bf[4][2];
#pragma unroll
            for (int i = 0; i < 4; i++)
                LDSM4(af[i][0], af[i][1], af[i][2], af[i][3],
                      sbase + aoff0 + (uint32_t)(i * 16 * SROW * 2 + s * 32));
#pragma unroll
            for (int jp = 0; jp < 2; jp++)
                LDSM4(bf[jp * 2][0], bf[jp * 2][1], bf[jp * 2 + 1][0],
                      bf[jp * 2 + 1][1],
                      sbase + boff0 + (uint32_t)(jp * 16 * SROW * 2 + s * 32));
#pragma unroll
            for (int i = 0; i < 4; i++)
#pragma unroll
                for (int j = 0; j < 4; j++) mma_f16(acc[i][j], af[i], bf[j]);
        }
    }

    if (mode == 0) {
#pragma unroll
        for (int i = 0; i < 4; i++)
#pragma unroll
            for (int j = 0; j < 4; j++) {
                int row = bm + wm * 64 + i * 16 + g;
                int col = bn + wn * 32 + j * 8 + 2 * tg;
                *(float2*)(C + (size_t)row * N + col) =
                    make_float2(acc[i][j][0], acc[i][j][1]);
                *(float2*)(C + (size_t)(row + 8) * N + col) =
                    make_float2(acc[i][j][2], acc[i][j][3]);
            }
    } else {
#pragma unroll
        for (int i = 0; i < 4; i++)
#pragma unroll
            for (int j = 0; j < 4; j++) {
                int row = bm + wm * 64 + i * 16 + g;
                int col = bn + wn * 32 + j * 8 + 2 * tg;
                qkv_store(row, col, acc[i][j][0], acc[i][j][1]);
                qkv_store(row + 8, col, acc[i][j][2], acc[i][j][3]);
            }
    }
}

// ---------------------------------------------------------------------------
// Sliding-window attention: one warp handles 4 adjacent queries of one head,
// sharing each K/V float4 load. Branchy online softmax. sink cancels; ignored.
// Output written as fp16 (feeds final GEMM directly).
// ---------------------------------------------------------------------------
__global__ void __launch_bounds__(256) attn_kernel(const float* __restrict__ Q,
                                                   const float* __restrict__ K,
                                                   const float* __restrict__ V) {
    const int warp = threadIdx.x >> 5;
    const int lane = threadIdx.x & 31;
    const int tq = (blockIdx.x * 8 + warp) * 4;
    const int h = blockIdx.y;
    const int kh = h >> 2;
    const float scale = 0.08838834764831845f;

    float4 q[4];
#pragma unroll
    for (int i = 0; i < 4; i++)
        q[i] = *(const float4*)(Q + (size_t)(tq + i) * C_DIM + h * HD + lane * 4);

    float m[4] = {-1e30f, -1e30f, -1e30f, -1e30f};
    float l[4] = {0.f, 0.f, 0.f, 0.f};
    float4 a[4];
#pragma unroll
    for (int i = 0; i < 4; i++) a[i] = make_float4(0.f, 0.f, 0.f, 0.f);

    int s0 = tq - WIN;      if (s0 < 0) s0 = 0;
    int s1 = tq + 3 + WIN;  if (s1 > T_SEQ - 1) s1 = T_SEQ - 1;

    for (int s = s0; s <= s1; s++) {
        float4 kv = *(const float4*)(K + (size_t)s * KV_DIM + kh * HD + lane * 4);
        float4 vv = *(const float4*)(V + (size_t)s * KV_DIM + kh * HD + lane * 4);
#pragma unroll
        for (int i = 0; i < 4; i++) {
            int t = tq + i;
            if (s < t - WIN || s > t + WIN) continue;  // warp-uniform
            float d = q[i].x * kv.x + q[i].y * kv.y + q[i].z * kv.z + q[i].w * kv.w;
#pragma unroll
            for (int o = 16; o > 0; o >>= 1) d += __shfl_xor_sync(0xffffffffu, d, o);
            d *= scale;
            if (d <= m[i]) {
                float p = __expf(d - m[i]);
                l[i] += p;
                a[i].x += p * vv.x;
                a[i].y += p * vv.y;
                a[i].z += p * vv.z;
                a[i].w += p * vv.w;
            } else {
                float corr = __expf(m[i] - d);
                m[i] = d;
                l[i] = l[i] * corr + 1.f;
                a[i].x = a[i].x * corr + vv.x;
                a[i].y = a[i].y * corr + vv.y;
                a[i].z = a[i].z * corr + vv.z;
                a[i].w = a[i].w * corr + vv.w;
            }
        }
    }
#pragma unroll
    for (int i = 0; i < 4; i++) {
        float inv = 1.f / l[i];
        __half2* ao = (__half2*)(g_AOH + (size_t)(tq + i) * C_DIM + h * HD + lane * 4);
        ao[0] = __floats2half2_rn(a[i].x * inv, a[i].y * inv);
        ao[1] = __floats2half2_rn(a[i].z * inv, a[i].w * inv);
    }
}

// ---------------------------------------------------------------------------
extern "C" void kernel_launch(void* const* d_in, const int* in_sizes, int n_in,
                              void* d_out, int out_size) {
    const float* x  = (const float*)d_in[0];
    const float* wq = (const float*)d_in[1];
    const float* wk = (const float*)d_in[2];
    const float* wv = (const float*)d_in[3];
    const float* wo = (const float*)d_in[4];
    // d_in[5] = sink: constant per softmax row -> cancels; ignored.
    float* out = (float*)d_out;

    float *Q, *Kp, *Vp;
    __half *XH, *WH, *WOH, *AOH;
    cudaGetSymbolAddress((void**)&Q,   g_Q);
    cudaGetSymbolAddress((void**)&Kp,  g_K);
    cudaGetSymbolAddress((void**)&Vp,  g_V);
    cudaGetSymbolAddress((void**)&XH,  g_XH);
    cudaGetSymbolAddress((void**)&WH,  g_WH);
    cudaGetSymbolAddress((void**)&WOH, g_WOH);
    cudaGetSymbolAddress((void**)&AOH, g_AOH);

    // one-time prep: rope table, fp16 conversions, weight transposes
    rc_kernel<<<(T_SEQ * HALF + 255) / 256, 256>>>();
    {
        int n4 = T_SEQ * C_DIM / 4;
        x_to_half<<<(n4 + 255) / 256, 256>>>((const float4*)x, n4);
        build_wt<<<dim3(KDIM / 32, QKV_N / 32), dim3(32, 8)>>>(wq, wk, wv);
        build_wot<<<dim3(KDIM / 32, C_DIM / 32), dim3(32, 8)>>>(wo);
    }

    cudaFuncSetAttribute(gemm_f16, cudaFuncAttributeMaxDynamicSharedMemorySize,
                         SMEM_BYTES);
    cudaFuncSetAttribute(gemm_f16, cudaFuncAttributePreferredSharedMemoryCarveout,
                         100);

    // QKV projection (fused, rope in epilogue)
    gemm_f16<<<dim3(QKV_N / 128, T_SEQ / 128), 256, SMEM_BYTES>>>(XH, WH, nullptr,
                                                                  QKV_N, 1);

    attn_kernel<<<dim3(T_SEQ / 32, NH), 256>>>(Q, Kp, Vp);

    // output projection
    gemm_f16<<<dim3(C_DIM / 128, T_SEQ / 128), 256, SMEM_BYTES>>>(AOH, WOH, out,
                                                                  C_DIM, 0);
}

// round 12
// speedup vs baseline: 1.0451x; 1.0451x over previous
#include <cuda_runtime.h>
#include <cuda_fp16.h>
#include <math.h>
#include <stdint.h>

#define T_SEQ 4096
#define C_DIM 2048
#define KV_DIM 512
#define QKV_N 3072
#define NH 16
#define NKV 4
#define HD 128
#define HALF 64
#define WIN 64
#define KDIM 2048
#define KT 64                 // 2048 / 32

// Scratch (no runtime allocation allowed)
__device__ float  g_Q[T_SEQ * C_DIM];
__device__ float  g_K[T_SEQ * KV_DIM];
__device__ float  g_V[T_SEQ * KV_DIM];
__device__ __half g_AOH[T_SEQ * C_DIM];        // attention output, fp16
__device__ __half g_XH[T_SEQ * C_DIM];         // x, fp16
__device__ __half g_WH[QKV_N * KDIM];          // [wq|wk|wv]^T  [N][K] fp16
__device__ __half g_WOH[C_DIM * KDIM];         // wo^T          [N][K] fp16
__device__ float2 g_RC[T_SEQ * HALF];          // rope (cos,sin) table

// ---------------------------------------------------------------------------
// One-time prep kernels
// ---------------------------------------------------------------------------
__global__ void rc_kernel() {
    int idx = blockIdx.x * blockDim.x + threadIdx.x;
    if (idx >= T_SEQ * HALF) return;
    int t = idx >> 6;
    int j = idx & 63;
    float inv = powf(10000.0f, -(float)j / (float)HALF);
    float s, c;
    sincosf((float)t * inv, &s, &c);
    g_RC[idx] = make_float2(c, s);
}

__global__ void x_to_half(const float4* __restrict__ src, int n4) {
    int i = blockIdx.x * blockDim.x + threadIdx.x;
    if (i >= n4) return;
    float4 v = src[i];
    __half2* dst = (__half2*)(g_XH + (size_t)i * 4);
    dst[0] = __floats2half2_rn(v.x, v.y);
    dst[1] = __floats2half2_rn(v.z, v.w);
}

// Transpose + convert: g_WH[n][k] = half(src[k][n]); src picked per n-region.
__global__ void build_wt(const float* __restrict__ wq, const float* __restrict__ wk,
                         const float* __restrict__ wv) {
    __shared__ float tile[32][33];
    int k0 = blockIdx.x * 32;
    int n0 = blockIdx.y * 32;
    int tx = threadIdx.x, ty = threadIdx.y;
    const float* src;
    int nb, noff;
    if (n0 < C_DIM)               { src = wq; nb = C_DIM;  noff = 0; }
    else if (n0 < C_DIM + KV_DIM) { src = wk; nb = KV_DIM; noff = C_DIM; }
    else                          { src = wv; nb = KV_DIM; noff = C_DIM + KV_DIM; }
#pragma unroll
    for (int j = 0; j < 4; j++)
        tile[ty + j * 8][tx] =
            src[(size_t)(k0 + ty + j * 8) * nb + (n0 - noff + tx)];
    __syncthreads();
#pragma unroll
    for (int j = 0; j < 4; j++)
        g_WH[(size_t)(n0 + ty + j * 8) * KDIM + k0 + tx] =
            __float2half(tile[tx][ty + j * 8]);
}

__global__ void build_wot(const float* __restrict__ wo) {
    __shared__ float tile[32][33];
    int k0 = blockIdx.x * 32;
    int n0 = blockIdx.y * 32;
    int tx = threadIdx.x, ty = threadIdx.y;
#pragma unroll
    for (int j = 0; j < 4; j++)
        tile[ty + j * 8][tx] = wo[(size_t)(k0 + ty + j * 8) * C_DIM + n0 + tx];
    __syncthreads();
#pragma unroll
    for (int j = 0; j < 4; j++)
        g_WOH[(size_t)(n0 + ty + j * 8) * KDIM + k0 + tx] =
            __float2half(tile[tx][ty + j * 8]);
}

// ---------------------------------------------------------------------------
// FP16 mma.sync GEMM with ldmatrix fragment loads + intra-tile fragment
// software pipelining. C[M,N] = A[M,K] @ Bt[N,K]^T, fp32 accumulate.
// CTA tile 128x128x32, 256 threads (8 warps 2x4), warp tile 64x32,
// mma.m16n8k16. Both tiles K-major, 40-half padded rows (conflict-free
// LDSM). cp.async 5-stage pipeline, 2 CTAs/SM.
// mode 0: plain fp32 store. mode 1: QKV epilogue (rope + route).
// ---------------------------------------------------------------------------
#define STAGES 5
#define SROW 40                               // halves per smem row
#define TILE_BYTES (128 * SROW * 2)           // 10240
#define STAGE_BYTES (2 * TILE_BYTES)          // 20480
#define SMEM_BYTES (STAGES * STAGE_BYTES)     // 102400

__device__ __forceinline__ void cp16(uint32_t dst, const __half* src) {
    asm volatile("cp.async.cg.shared.global [%0], [%1], 16;\n" :: "r"(dst), "l"(src));
}

#define LDSM4(r0, r1, r2, r3, addr)                                            \
    asm volatile("ldmatrix.sync.aligned.m8n8.x4.shared.b16 {%0,%1,%2,%3}, [%4];" \
                 : "=r"(r0), "=r"(r1), "=r"(r2), "=r"(r3) : "r"(addr))

__device__ __forceinline__ void mma_f16(float c[4], const uint32_t a[4],
                                        const uint32_t b[2]) {
    asm volatile(
        "mma.sync.aligned.m16n8k16.row.col.f32.f16.f16.f32 "
        "{%0,%1,%2,%3}, {%4,%5,%6,%7}, {%8,%9}, {%0,%1,%2,%3};\n"
        : "+f"(c[0]), "+f"(c[1]), "+f"(c[2]), "+f"(c[3])
        : "r"(a[0]), "r"(a[1]), "r"(a[2]), "r"(a[3]), "r"(b[0]), "r"(b[1]));
}

__device__ __forceinline__ void ld_frags(uint32_t sbase, uint32_t aoff0,
                                         uint32_t boff0, int s,
                                         uint32_t af[4][4], uint32_t bf[4][2]) {
#pragma unroll
    for (int i = 0; i < 4; i++)
        LDSM4(af[i][0], af[i][1], af[i][2], af[i][3],
              sbase + aoff0 + (uint32_t)(i * 16 * SROW * 2 + s * 32));
#pragma unroll
    for (int jp = 0; jp < 2; jp++)
        LDSM4(bf[jp * 2][0], bf[jp * 2][1], bf[jp * 2 + 1][0], bf[jp * 2 + 1][1],
              sbase + boff0 + (uint32_t)(jp * 16 * SROW * 2 + s * 32));
}

__device__ __forceinline__ void qkv_store(int t, int col, float v0, float v1) {
    if (col < C_DIM) {
        int jj = (col & 127) >> 1;
        float2 cs = g_RC[t * HALF + jj];
        *(float2*)&g_Q[(size_t)t * C_DIM + col] =
            make_float2(v0 * cs.x - v1 * cs.y, v0 * cs.y + v1 * cs.x);
    } else if (col < C_DIM + KV_DIM) {
        int kc = col - C_DIM;
        int jj = (kc & 127) >> 1;
        float2 cs = g_RC[t * HALF + jj];
        *(float2*)&g_K[(size_t)t * KV_DIM + kc] =
            make_float2(v0 * cs.x - v1 * cs.y, v0 * cs.y + v1 * cs.x);
    } else {
        int vc = col - C_DIM - KV_DIM;
        *(float2*)&g_V[(size_t)t * KV_DIM + vc] = make_float2(v0, v1);
    }
}

__global__ void __launch_bounds__(256, 2) gemm_f16(const __half* __restrict__ A,
                                                   const __half* __restrict__ Bt,
                                                   float* __restrict__ C,
                                                   int N, int mode) {
    extern __shared__ char smem[];
    uint32_t smem_u;
    asm("{.reg .u64 t; cvta.to.shared.u64 t, %1; cvt.u32.u64 %0, t;}"
        : "=r"(smem_u) : "l"(smem));

    const int tid = threadIdx.x;
    const int bm = blockIdx.y * 128;
    const int bn = blockIdx.x * 128;
    const int warp = tid >> 5;
    const int lane = tid & 31;
    const int wm = warp >> 2;     // 0..1
    const int wn = warp & 3;      // 0..3
    const int g  = lane >> 2;     // 0..7
    const int tg = lane & 3;      // 0..3

    // ldmatrix per-lane address constants (byte offsets within stage)
    const int mi = lane >> 3;     // matrix index 0..3
    const int rw = lane & 7;      // row within matrix
    const uint32_t aoff0 =
        (uint32_t)(((wm * 64 + ((mi & 1) << 3) + rw) * SROW + ((mi >> 1) << 3)) * 2);
    const uint32_t boff0 =
        (uint32_t)(((wn * 32 + ((mi >> 1) << 3) + rw) * SROW + ((mi & 1) << 3)) * 2) +
        TILE_BYTES;

    // loader mapping: 2 tiles x 128 rows x 4 chunks(16B); 4 cp16 per thread
    const int row4 = tid >> 2;    // 0..63 (+64 for second pass)
    const int ch   = tid & 3;
    const __half* ap = A + (size_t)(bm + row4) * KDIM + ch * 8;
    const __half* bp = Bt + (size_t)(bn + row4) * KDIM + ch * 8;
    const uint32_t soff = (uint32_t)((row4 * SROW + ch * 8) * 2);

    float acc[4][4][4];
#pragma unroll
    for (int i = 0; i < 4; i++)
#pragma unroll
        for (int j = 0; j < 4; j++)
#pragma unroll
            for (int r = 0; r < 4; r++) acc[i][j][r] = 0.f;

    // prologue: stages 0..STAGES-2
#pragma unroll
    for (int s = 0; s < STAGES - 1; s++) {
        uint32_t base = smem_u + (uint32_t)s * STAGE_BYTES;
        cp16(base + soff, ap);
        cp16(base + soff + 64 * SROW * 2, ap + (size_t)64 * KDIM);
        cp16(base + TILE_BYTES + soff, bp);
        cp16(base + TILE_BYTES + soff + 64 * SROW * 2, bp + (size_t)64 * KDIM);
        asm volatile("cp.async.commit_group;\n" ::);
        ap += 32;
        bp += 32;
    }

    int st = 0;
    int wst = STAGES - 1;
    for (int kt = 0; kt < KT; kt++) {
        // wait: stage kt's group must be complete (N = min(STAGES-2, KT-1-kt))
        if (kt < KT - 3)
            asm volatile("cp.async.wait_group 3;\n" ::);
        else if (kt == KT - 3)
            asm volatile("cp.async.wait_group 2;\n" ::);
        else if (kt == KT - 2)
            asm volatile("cp.async.wait_group 1;\n" ::);
        else
            asm volatile("cp.async.wait_group 0;\n" ::);
        __syncthreads();

        if (kt + STAGES - 1 < KT) {
            uint32_t base = smem_u + (uint32_t)wst * STAGE_BYTES;
            cp16(base + soff, ap);
            cp16(base + soff + 64 * SROW * 2, ap + (size_t)64 * KDIM);
            cp16(base + TILE_BYTES + soff, bp);
            cp16(base + TILE_BYTES + soff + 64 * SROW * 2, bp + (size_t)64 * KDIM);
            asm volatile("cp.async.commit_group;\n" ::);
            ap += 32;
            bp += 32;
            wst = (wst == STAGES - 1) ? 0 : wst + 1;
        }

        const uint32_t sbase = smem_u + (uint32_t)st * STAGE_BYTES;
        st = (st == STAGES - 1) ? 0 : st + 1;

        // software-pipelined fragment loads: load s=0, then load s=1 while
        // computing s=0's MMAs, then compute s=1.
        uint32_t af0[4][4], bf0[4][2], af1[4][4], bf1[4][2];
        ld_frags(sbase, aoff0, boff0, 0, af0, bf0);
        ld_frags(sbase, aoff0, boff0, 1, af1, bf1);
#pragma unroll
        for (int i = 0; i < 4; i++)
#pragma unroll
            for (int j = 0; j < 4; j++) mma_f16(acc[i][j], af0[i], bf0[j]);
#pragma unroll
        for (int i = 0; i < 4; i++)
#pragma unroll
            for (int j = 0; j < 4; j++) mma_f16(acc[i][j], af1[i], bf1[j]);
    }

    if (mode == 0) {
#pragma unroll
        for (int i = 0; i < 4; i++)
#pragma unroll
            for (int j = 0; j < 4; j++) {
                int row = bm + wm * 64 + i * 16 + g;
                int col = bn + wn * 32 + j * 8 + 2 * tg;
                *(float2*)(C + (size_t)row * N + col) =
                    make_float2(acc[i][j][0], acc[i][j][1]);
                *(float2*)(C + (size_t)(row + 8) * N + col) =
                    make_float2(acc[i][j][2], acc[i][j][3]);
            }
    } else {
#pragma unroll
        for (int i = 0; i < 4; i++)
#pragma unroll
            for (int j = 0; j < 4; j++) {
                int row = bm + wm * 64 + i * 16 + g;
                int col = bn + wn * 32 + j * 8 + 2 * tg;
                qkv_store(row, col, acc[i][j][0], acc[i][j][1]);
                qkv_store(row + 8, col, acc[i][j][2], acc[i][j][3]);
            }
    }
}

// ---------------------------------------------------------------------------
// Sliding-window attention: one warp handles 4 adjacent queries of one head,
// sharing each K/V float4 load. Branchy online softmax. sink cancels; ignored.
// Output written as fp16 (feeds final GEMM directly).
// ---------------------------------------------------------------------------
__global__ void __launch_bounds__(256) attn_kernel(const float* __restrict__ Q,
                                                   const float* __restrict__ K,
                                                   const float* __restrict__ V) {
    const int warp = threadIdx.x >> 5;
    const int lane = threadIdx.x & 31;
    const int tq = (blockIdx.x * 8 + warp) * 4;
    const int h = blockIdx.y;
    const int kh = h >> 2;
    const float scale = 0.08838834764831845f;

    float4 q[4];
#pragma unroll
    for (int i = 0; i < 4; i++)
        q[i] = *(const float4*)(Q + (size_t)(tq + i) * C_DIM + h * HD + lane * 4);

    float m[4] = {-1e30f, -1e30f, -1e30f, -1e30f};
    float l[4] = {0.f, 0.f, 0.f, 0.f};
    float4 a[4];
#pragma unroll
    for (int i = 0; i < 4; i++) a[i] = make_float4(0.f, 0.f, 0.f, 0.f);

    int s0 = tq - WIN;      if (s0 < 0) s0 = 0;
    int s1 = tq + 3 + WIN;  if (s1 > T_SEQ - 1) s1 = T_SEQ - 1;

    for (int s = s0; s <= s1; s++) {
        float4 kv = *(const float4*)(K + (size_t)s * KV_DIM + kh * HD + lane * 4);
        float4 vv = *(const float4*)(V + (size_t)s * KV_DIM + kh * HD + lane * 4);
#pragma unroll
        for (int i = 0; i < 4; i++) {
            int t = tq + i;
            if (s < t - WIN || s > t + WIN) continue;  // warp-uniform
            float d = q[i].x * kv.x + q[i].y * kv.y + q[i].z * kv.z + q[i].w * kv.w;
#pragma unroll
            for (int o = 16; o > 0; o >>= 1) d += __shfl_xor_sync(0xffffffffu, d, o);
            d *= scale;
            if (d <= m[i]) {
                float p = __expf(d - m[i]);
                l[i] += p;
                a[i].x += p * vv.x;
                a[i].y += p * vv.y;
                a[i].z += p * vv.z;
                a[i].w += p * vv.w;
            } else {
                float corr = __expf(m[i] - d);
                m[i] = d;
                l[i] = l[i] * corr + 1.f;
                a[i].x = a[i].x * corr + vv.x;
                a[i].y = a[i].y * corr + vv.y;
                a[i].z = a[i].z * corr + vv.z;
                a[i].w = a[i].w * corr + vv.w;
            }
        }
    }
#pragma unroll
    for (int i = 0; i < 4; i++) {
        float inv = 1.f / l[i];
        __half2* ao = (__half2*)(g_AOH + (size_t)(tq + i) * C_DIM + h * HD + lane * 4);
        ao[0] = __floats2half2_rn(a[i].x * inv, a[i].y * inv);
        ao[1] = __floats2half2_rn(a[i].z * inv, a[i].w * inv);
    }
}

// ---------------------------------------------------------------------------
extern "C" void kernel_launch(void* const* d_in, const int* in_sizes, int n_in,
                              void* d_out, int out_size) {
    const float* x  = (const float*)d_in[0];
    const float* wq = (const float*)d_in[1];
    const float* wk = (const float*)d_in[2];
    const float* wv = (const float*)d_in[3];
    const float* wo = (const float*)d_in[4];
    // d_in[5] = sink: constant per softmax row -> cancels; ignored.
    float* out = (float*)d_out;

    float *Q, *Kp, *Vp;
    __half *XH, *WH, *WOH, *AOH;
    cudaGetSymbolAddress((void**)&Q,   g_Q);
    cudaGetSymbolAddress((void**)&Kp,  g_K);
    cudaGetSymbolAddress((void**)&Vp,  g_V);
    cudaGetSymbolAddress((void**)&XH,  g_XH);
    cudaGetSymbolAddress((void**)&WH,  g_WH);
    cudaGetSymbolAddress((void**)&WOH, g_WOH);
    cudaGetSymbolAddress((void**)&AOH, g_AOH);

    // one-time prep: rope table, fp16 conversions, weight transposes
    rc_kernel<<<(T_SEQ * HALF + 255) / 256, 256>>>();
    {
        int n4 = T_SEQ * C_DIM / 4;
        x_to_half<<<(n4 + 255) / 256, 256>>>((const float4*)x, n4);
        build_wt<<<dim3(KDIM / 32, QKV_N / 32), dim3(32, 8)>>>(wq, wk, wv);
        build_wot<<<dim3(KDIM / 32, C_DIM / 32), dim3(32, 8)>>>(wo);
    }

    cudaFuncSetAttribute(gemm_f16, cudaFuncAttributeMaxDynamicSharedMemorySize,
                         SMEM_BYTES);
    cudaFuncSetAttribute(gemm_f16, cudaFuncAttributePreferredSharedMemoryCarveout,
                         100);

    // QKV projection (fused, rope in epilogue)
    gemm_f16<<<dim3(QKV_N / 128, T_SEQ / 128), 256, SMEM_BYTES>>>(XH, WH, nullptr,
                                                                  QKV_N, 1);

    attn_kernel<<<dim3(T_SEQ / 32, NH), 256>>>(Q, Kp, Vp);

    // output projection
    gemm_f16<<<dim3(C_DIM / 128, T_SEQ / 128), 256, SMEM_BYTES>>>(AOH, WOH, out,
                                                                  C_DIM, 0);
}